// round 2
// baseline (speedup 1.0000x reference)
#include <cuda_runtime.h>
#include <cstdint>

#define D 128
#define MAXN 100000
#define MAXE 1600000

typedef unsigned long long ull;

// ---------------- scratch (static device mem, no allocs) -------------------
__device__ float g_Wt[D * D];        // W transposed, k-major
__device__ int   g_cnt[MAXN];        // histogram -> fill cursors
__device__ int   g_off[MAXN + 1];    // CSR row offsets
__device__ int   g_csr[MAXE];        // edge src ids grouped by dst
__device__ int   g_blk[256];         // scan block partials

// ---------------- f32x2 packed-FMA helpers (sm_103a FFMA2) -----------------
__device__ __forceinline__ ull splat2(float x) {
    ull r; asm("mov.b64 %0, {%1, %1};" : "=l"(r) : "f"(x)); return r;
}
__device__ __forceinline__ void fma2(ull& d, ull a, ull b) {
    asm("fma.rn.f32x2 %0, %1, %2, %0;" : "+l"(d) : "l"(a), "l"(b));
}
__device__ __forceinline__ float2 unpack2(ull v) {
    float2 f; asm("mov.b64 {%0, %1}, %2;" : "=f"(f.x), "=f"(f.y) : "l"(v)); return f;
}

// ---------------------------------------------------------------------------
// Kernel: transpose W into g_Wt  (tiny)
// ---------------------------------------------------------------------------
__global__ void k_transpose(const float* __restrict__ W) {
    int idx = blockIdx.x * blockDim.x + threadIdx.x;
    if (idx < D * D) {
        int k = idx / D, n = idx % D;
        g_Wt[idx] = W[n * D + k];
    }
}

// ---------------------------------------------------------------------------
// CSR build: zero counts -> histogram -> 3-phase exclusive scan -> fill
// ---------------------------------------------------------------------------
__global__ void k_zero_cnt(int n) {
    int i = blockIdx.x * blockDim.x + threadIdx.x;
    if (i < n) g_cnt[i] = 0;
}

__global__ void k_hist(const int* __restrict__ dst, int E) {
    int i = blockIdx.x * blockDim.x + threadIdx.x;
    int stride = gridDim.x * blockDim.x;
    for (; i < E; i += stride) atomicAdd(&g_cnt[dst[i]], 1);
}

// scan phase 1: per-block (1024 elems, 256 thr x 4) exclusive scan + partials
__global__ void k_scan1(int n) {
    __shared__ int wsum[8];
    int b = blockIdx.x, t = threadIdx.x;
    int base = b * 1024 + t * 4;
    int v0 = (base + 0 < n) ? g_cnt[base + 0] : 0;
    int v1 = (base + 1 < n) ? g_cnt[base + 1] : 0;
    int v2 = (base + 2 < n) ? g_cnt[base + 2] : 0;
    int v3 = (base + 3 < n) ? g_cnt[base + 3] : 0;
    int s = v0 + v1 + v2 + v3;

    int lane = t & 31, w = t >> 5;
    int inc = s;
#pragma unroll
    for (int o = 1; o < 32; o <<= 1) {
        int x = __shfl_up_sync(0xffffffffu, inc, o);
        if (lane >= o) inc += x;
    }
    if (lane == 31) wsum[w] = inc;
    __syncthreads();
    if (t == 0) {
        int run = 0;
#pragma unroll
        for (int i = 0; i < 8; i++) { int tmp = wsum[i]; wsum[i] = run; run += tmp; }
        g_blk[b] = run;
    }
    __syncthreads();
    int excl = wsum[w] + inc - s;
    if (base + 0 < n) g_off[base + 0] = excl;
    if (base + 1 < n) g_off[base + 1] = excl + v0;
    if (base + 2 < n) g_off[base + 2] = excl + v0 + v1;
    if (base + 3 < n) g_off[base + 3] = excl + v0 + v1 + v2;
}

// scan phase 2: exclusive scan of block partials (nb <= 128), single block
__global__ void k_scan2(int nb) {
    __shared__ int s[256];
    int t = threadIdx.x;
    s[t] = (t < nb) ? g_blk[t] : 0;
    __syncthreads();
    if (t == 0) {
        int run = 0;
        for (int i = 0; i < nb; i++) { int tmp = s[i]; s[i] = run; run += tmp; }
    }
    __syncthreads();
    if (t < nb) g_blk[t] = s[t];
}

// scan phase 3: add partials, copy starts into g_cnt as fill cursors
__global__ void k_scan3(int n, int E) {
    int i = blockIdx.x * blockDim.x + threadIdx.x;
    if (i < n) {
        int v = g_off[i] + g_blk[i >> 10];
        g_off[i] = v;
        g_cnt[i] = v;
    }
    if (i == 0) g_off[n] = E;
}

__global__ void k_fill(const int* __restrict__ src, const int* __restrict__ dst, int E) {
    int i = blockIdx.x * blockDim.x + threadIdx.x;
    int stride = gridDim.x * blockDim.x;
    for (; i < E; i += stride) {
        int pos = atomicAdd(&g_cnt[dst[i]], 1);
        g_csr[pos] = src[i];
    }
}

// ---------------------------------------------------------------------------
// Gather: acc[n] = sum over CSR edges of h[src], plain stores (no atomics).
// One warp per node, lane owns 4 contiguous floats; unroll-2 for MLP.
// Writes every output row -> no separate zero kernel needed.
// ---------------------------------------------------------------------------
__global__ void k_gather(const float* __restrict__ h, float* __restrict__ acc, int N) {
    int nwarp = blockIdx.x * 8 + (threadIdx.x >> 5);
    if (nwarp >= N) return;
    int lane = threadIdx.x & 31;

    int beg = g_off[nwarp];
    int end = g_off[nwarp + 1];

    float4 a0 = make_float4(0.f, 0.f, 0.f, 0.f);
    float4 a1 = make_float4(0.f, 0.f, 0.f, 0.f);

    int e = beg;
    for (; e + 1 < end; e += 2) {
        int s0 = g_csr[e];
        int s1 = g_csr[e + 1];
        float4 v0 = *(const float4*)(h + (size_t)s0 * D + lane * 4);
        float4 v1 = *(const float4*)(h + (size_t)s1 * D + lane * 4);
        a0.x += v0.x; a0.y += v0.y; a0.z += v0.z; a0.w += v0.w;
        a1.x += v1.x; a1.y += v1.y; a1.z += v1.z; a1.w += v1.w;
    }
    if (e < end) {
        int s0 = g_csr[e];
        float4 v0 = *(const float4*)(h + (size_t)s0 * D + lane * 4);
        a0.x += v0.x; a0.y += v0.y; a0.z += v0.z; a0.w += v0.w;
    }
    float4 o;
    o.x = a0.x + a1.x; o.y = a0.y + a1.y; o.z = a0.z + a1.z; o.w = a0.w + a1.w;
    *(float4*)(acc + (size_t)nwarp * D + lane * 4) = o;
}

// ---------------------------------------------------------------------------
// GEMM: out = relu(acc @ W^T + b), in place, packed f32x2 FMA (FFMA2).
// 256 threads, 64-row tile, full Wt (64KB) in smem, A-tile stored k-major
// (transposed) so row-PAIRS load as one LDS.64 -> packed operand for free.
// Each thread: 4 row-pairs x 4 cols = 16 b64 accumulators = 32 outputs.
// ---------------------------------------------------------------------------
#define GM_BM 64
#define GM_BK 16
#define GM_SMEM_BYTES ((D * D + GM_BK * GM_BM) * 4)  // 69632

__global__ void k_gemm(const float* __restrict__ A,     // [M,128] (== out)
                       const float* __restrict__ bias,  // [128]
                       float* __restrict__ out, int M) {
    extern __shared__ float sm[];
    float* Ws  = sm;            // [128][128] Wt, k-major
    float* AsT = sm + D * D;    // [BK][BM]  (k-major, rows adjacent)

    int tid = threadIdx.x;
    for (int i = tid * 4; i < D * D; i += 256 * 4)
        *(float4*)(Ws + i) = *(const float4*)(g_Wt + i);

    int m0 = blockIdx.x * GM_BM;
    int tx = tid & 31;   // cols tx*4 .. tx*4+3
    int ty = tid >> 5;   // rows ty*8 .. ty*8+7 (4 pairs)

    ull acc[4][4];
#pragma unroll
    for (int p = 0; p < 4; p++)
#pragma unroll
        for (int c = 0; c < 4; c++) acc[p][c] = 0ull;

    int lr = tid >> 2;          // load row 0..63
    int lc = (tid & 3) * 4;     // load col 0,4,8,12

    __syncthreads();

    for (int k0 = 0; k0 < D; k0 += GM_BK) {
        int gm = m0 + lr;
        float4 av = make_float4(0.f, 0.f, 0.f, 0.f);
        if (gm < M) av = *(const float4*)(A + (size_t)gm * D + k0 + lc);
        __syncthreads();
        // store transposed: AsT[k][m]
        AsT[(lc + 0) * GM_BM + lr] = av.x;
        AsT[(lc + 1) * GM_BM + lr] = av.y;
        AsT[(lc + 2) * GM_BM + lr] = av.z;
        AsT[(lc + 3) * GM_BM + lr] = av.w;
        __syncthreads();

#pragma unroll
        for (int kk = 0; kk < GM_BK; kk++) {
            float4 bv = *(const float4*)(Ws + (k0 + kk) * D + tx * 4);
            ull b0 = splat2(bv.x), b1 = splat2(bv.y),
                b2 = splat2(bv.z), b3 = splat2(bv.w);
            const float* ar = AsT + kk * GM_BM + ty * 8;
            ull a0 = *(const ull*)(ar + 0);
            ull a1 = *(const ull*)(ar + 2);
            ull a2 = *(const ull*)(ar + 4);
            ull a3 = *(const ull*)(ar + 6);
            fma2(acc[0][0], a0, b0); fma2(acc[0][1], a0, b1);
            fma2(acc[0][2], a0, b2); fma2(acc[0][3], a0, b3);
            fma2(acc[1][0], a1, b0); fma2(acc[1][1], a1, b1);
            fma2(acc[1][2], a1, b2); fma2(acc[1][3], a1, b3);
            fma2(acc[2][0], a2, b0); fma2(acc[2][1], a2, b1);
            fma2(acc[2][2], a2, b2); fma2(acc[2][3], a2, b3);
            fma2(acc[3][0], a3, b0); fma2(acc[3][1], a3, b1);
            fma2(acc[3][2], a3, b2); fma2(acc[3][3], a3, b3);
        }
    }

    float4 bb = *(const float4*)(bias + tx * 4);
#pragma unroll
    for (int p = 0; p < 4; p++) {
        float2 c0 = unpack2(acc[p][0]);
        float2 c1 = unpack2(acc[p][1]);
        float2 c2 = unpack2(acc[p][2]);
        float2 c3 = unpack2(acc[p][3]);
        int r0 = m0 + ty * 8 + 2 * p;
        if (r0 < M) {
            float4 o;
            o.x = fmaxf(c0.x + bb.x, 0.f);
            o.y = fmaxf(c1.x + bb.y, 0.f);
            o.z = fmaxf(c2.x + bb.z, 0.f);
            o.w = fmaxf(c3.x + bb.w, 0.f);
            *(float4*)(out + (size_t)r0 * D + tx * 4) = o;
        }
        int r1 = r0 + 1;
        if (r1 < M) {
            float4 o;
            o.x = fmaxf(c0.y + bb.x, 0.f);
            o.y = fmaxf(c1.y + bb.y, 0.f);
            o.z = fmaxf(c2.y + bb.z, 0.f);
            o.w = fmaxf(c3.y + bb.w, 0.f);
            *(float4*)(out + (size_t)r1 * D + tx * 4) = o;
        }
    }
}

// ---------------------------------------------------------------------------
// Launch
// ---------------------------------------------------------------------------
extern "C" void kernel_launch(void* const* d_in, const int* in_sizes, int n_in,
                              void* d_out, int out_size) {
    const float* h    = (const float*)d_in[0];
    const int*   esrc = (const int*)d_in[1];
    const int*   edst = (const int*)d_in[2];
    const float* W    = (const float*)d_in[3];
    const float* b    = (const float*)d_in[4];
    float* out = (float*)d_out;

    int M = in_sizes[0] / D;   // 100000 nodes
    int E = in_sizes[1];       // 1600000 edges

    cudaFuncSetAttribute(k_gemm, cudaFuncAttributeMaxDynamicSharedMemorySize,
                         GM_SMEM_BYTES);

    int nb = (M + 1023) / 1024;                       // scan blocks (98)

    k_transpose<<<(D * D + 255) / 256, 256>>>(W);
    k_zero_cnt<<<(M + 255) / 256, 256>>>(M);
    k_hist<<<1024, 256>>>(edst, E);
    k_scan1<<<nb, 256>>>(M);
    k_scan2<<<1, 256>>>(nb);
    k_scan3<<<(M + 255) / 256, 256>>>(M, E);
    k_fill<<<1024, 256>>>(esrc, edst, E);
    k_gather<<<(M + 7) / 8, 256>>>(h, out, M);
    k_gemm<<<(M + GM_BM - 1) / GM_BM, 256, GM_SMEM_BYTES>>>(out, b, out, M);
}

// round 4
// speedup vs baseline: 1.0391x; 1.0391x over previous
#include <cuda_runtime.h>
#include <cuda_bf16.h>
#include <cstdint>

#define D 128
#define PADK 136            // padded bf16 row stride (conflict-free fragments)
#define W_IMG_U32 (128 * PADK / 2)   // 8704 u32 per image

// ---------------- scratch (static device mem) ------------------------------
__device__ unsigned g_Whi[W_IMG_U32];   // W bf16-hi, [n][PADK] layout
__device__ unsigned g_Wlo[W_IMG_U32];   // W bf16-lo

// ---------------------------------------------------------------------------
// bf16 pack helpers
// ---------------------------------------------------------------------------
__device__ __forceinline__ unsigned pack_bf16x2(__nv_bfloat16 a, __nv_bfloat16 b) {
    return ((unsigned)*(unsigned short*)&a) | ((unsigned)*(unsigned short*)&b << 16);
}

// ---------------------------------------------------------------------------
// Kernel: W -> bf16 hi/lo padded images (tiny, once)
// ---------------------------------------------------------------------------
__global__ void k_prepw(const float* __restrict__ W) {
    int n = threadIdx.x;                    // 128 threads, one W row each
    char* phi = (char*)g_Whi;
    char* plo = (char*)g_Wlo;
    for (int k = 0; k < D; k += 2) {
        float f0 = W[n * D + k], f1 = W[n * D + k + 1];
        __nv_bfloat16 h0 = __float2bfloat16(f0);
        __nv_bfloat16 h1 = __float2bfloat16(f1);
        __nv_bfloat16 l0 = __float2bfloat16(f0 - __bfloat162float(h0));
        __nv_bfloat16 l1 = __float2bfloat16(f1 - __bfloat162float(h1));
        unsigned off = (unsigned)(n * PADK + k) * 2;
        *(unsigned*)(phi + off) = pack_bf16x2(h0, h1);
        *(unsigned*)(plo + off) = pack_bf16x2(l0, l1);
    }
}

// ---------------------------------------------------------------------------
// Kernel: zero accumulator (lives in d_out)
// ---------------------------------------------------------------------------
__global__ void k_zero(float4* __restrict__ out, int n4) {
    int i = blockIdx.x * blockDim.x + threadIdx.x;
    int stride = gridDim.x * blockDim.x;
    float4 z = make_float4(0.f, 0.f, 0.f, 0.f);
    for (; i < n4; i += stride) out[i] = z;
}

// ---------------------------------------------------------------------------
// Kernel: edge scatter-sum (proven R1). red.global.add.v4.f32.
// ---------------------------------------------------------------------------
__device__ __forceinline__ void red_add_v4(float* addr, float4 v) {
    asm volatile("red.global.add.v4.f32 [%0], {%1,%2,%3,%4};"
                 :: "l"(addr), "f"(v.x), "f"(v.y), "f"(v.z), "f"(v.w)
                 : "memory");
}

__global__ void k_scatter(const float* __restrict__ h,
                          const int* __restrict__ src,
                          const int* __restrict__ dst,
                          float* __restrict__ acc, int E) {
    int warp = (blockIdx.x * blockDim.x + threadIdx.x) >> 5;
    int lane = threadIdx.x & 31;
    int base = warp * 32;
    if (base >= E) return;

    int e = base + lane;
    int s = 0, d = 0;
    if (e < E) { s = src[e]; d = dst[e]; }
    int cnt = min(32, E - base);

    for (int i = 0; i < cnt; i++) {
        int si = __shfl_sync(0xffffffffu, s, i);
        int di = __shfl_sync(0xffffffffu, d, i);
        float4 v = *(const float4*)(h + (size_t)si * D + lane * 4);
        red_add_v4(acc + (size_t)di * D + lane * 4, v);
    }
}

// ---------------------------------------------------------------------------
// Tensor-core GEMM via mma.sync (HMMA): out = relu(acc @ W^T + b), in place.
// CTA: 128 rows x 128 cols, 256 threads = 8 warps (4 m x 2 n), warp 32x64.
// 2-term bf16 split, fp32 accum: Ahi*Whi + Ahi*Wlo + Alo*Whi.
// smem: Whi | Wlo | Ahi | Alo (bf16, [row][PADK]); Cs (f32) overlays Ahi/Alo
// for the coalesced epilogue. bias at the end.
// ---------------------------------------------------------------------------
#define SM_WHI 0
#define SM_WLO (SM_WHI + 128 * PADK * 2)      // 34816
#define SM_AHI (SM_WLO + 128 * PADK * 2)      // 69632
#define SM_ALO (SM_AHI + 128 * PADK * 2)      // 104448
#define SM_BIAS (SM_ALO + 128 * PADK * 2)     // 139264
#define SM_TOTAL (SM_BIAS + 512)              // 139776
#define SM_CS SM_AHI                          // f32 [128][132] = 67584 <= 69632
#define CS_STRIDE 132

__device__ __forceinline__ void mma_bf16(float& c0, float& c1, float& c2, float& c3,
                                         unsigned a0, unsigned a1, unsigned a2, unsigned a3,
                                         unsigned b0, unsigned b1) {
    asm volatile(
        "mma.sync.aligned.m16n8k16.row.col.f32.bf16.bf16.f32 "
        "{%0,%1,%2,%3}, {%4,%5,%6,%7}, {%8,%9}, {%0,%1,%2,%3};"
        : "+f"(c0), "+f"(c1), "+f"(c2), "+f"(c3)
        : "r"(a0), "r"(a1), "r"(a2), "r"(a3), "r"(b0), "r"(b1));
}

__global__ void __launch_bounds__(256, 1)
k_gemm_mma(const float* __restrict__ A,      // [M,128] (== out)
           const float* __restrict__ bias,   // [128]
           float* __restrict__ out, int M) {
    extern __shared__ char sm[];
    int tid = threadIdx.x;
    int wid = tid >> 5;
    int lane = tid & 31;
    int m0 = blockIdx.x * 128;

    // stage bias
    if (tid < 128) *(float*)(sm + SM_BIAS + tid * 4) = bias[tid];

    // copy W hi/lo images (linear uint4, L2-broadcast across CTAs)
    {
        const uint4* shi = (const uint4*)g_Whi;
        const uint4* slo = (const uint4*)g_Wlo;
        uint4* dhi = (uint4*)(sm + SM_WHI);
        uint4* dlo = (uint4*)(sm + SM_WLO);
        for (int i = tid; i < W_IMG_U32 / 4; i += 256) {
            dhi[i] = shi[i];
            dlo[i] = slo[i];
        }
    }

    // load + split A tile: thread -> row (tid>>1), col half 64*(tid&1)
    {
        int row = tid >> 1;
        int cbase = (tid & 1) * 64;
        int gm = m0 + row;
        char* ahi = sm + SM_AHI;
        char* alo = sm + SM_ALO;
        if (gm < M) {
            const float4* arow = (const float4*)(A + (size_t)gm * D + cbase);
#pragma unroll
            for (int i = 0; i < 16; i++) {
                float4 v = arow[i];
                int c = cbase + i * 4;
                __nv_bfloat16 h0 = __float2bfloat16(v.x);
                __nv_bfloat16 h1 = __float2bfloat16(v.y);
                __nv_bfloat16 h2 = __float2bfloat16(v.z);
                __nv_bfloat16 h3 = __float2bfloat16(v.w);
                __nv_bfloat16 l0 = __float2bfloat16(v.x - __bfloat162float(h0));
                __nv_bfloat16 l1 = __float2bfloat16(v.y - __bfloat162float(h1));
                __nv_bfloat16 l2 = __float2bfloat16(v.z - __bfloat162float(h2));
                __nv_bfloat16 l3 = __float2bfloat16(v.w - __bfloat162float(h3));
                unsigned o = (unsigned)(row * PADK + c) * 2;
                *(unsigned*)(ahi + o)     = pack_bf16x2(h0, h1);
                *(unsigned*)(ahi + o + 4) = pack_bf16x2(h2, h3);
                *(unsigned*)(alo + o)     = pack_bf16x2(l0, l1);
                *(unsigned*)(alo + o + 4) = pack_bf16x2(l2, l3);
            }
        } else {
#pragma unroll
            for (int i = 0; i < 16; i++) {
                unsigned o = (unsigned)(row * PADK + cbase + i * 4) * 2;
                *(uint2*)(ahi + o) = make_uint2(0u, 0u);
                *(uint2*)(alo + o) = make_uint2(0u, 0u);
            }
        }
    }
    __syncthreads();

    // warp tile: warp_m = wid&3 (rows *32), warp_n = wid>>2 (cols *64)
    int wm = (wid & 3) * 32;
    int wn = (wid >> 2) * 64;
    int g = lane >> 2;        // group id 0..7
    int t = lane & 3;         // thread-in-group 0..3

    float acc[2][8][4];
#pragma unroll
    for (int mt = 0; mt < 2; mt++)
#pragma unroll
        for (int nt = 0; nt < 8; nt++)
#pragma unroll
            for (int i = 0; i < 4; i++) acc[mt][nt][i] = 0.f;

    const char* Aimg[3] = { sm + SM_AHI, sm + SM_AHI, sm + SM_ALO };
    const char* Wimg[3] = { sm + SM_WHI, sm + SM_WLO, sm + SM_WHI };

    for (int p = 0; p < 3; p++) {
        const char* As = Aimg[p];
        const char* Ws = Wimg[p];
#pragma unroll
        for (int ks = 0; ks < 8; ks++) {
            int k0 = ks * 16;
            unsigned a[2][4];
#pragma unroll
            for (int mt = 0; mt < 2; mt++) {
                unsigned base = (unsigned)((wm + mt * 16 + g) * PADK + k0 + 2 * t) * 2;
                a[mt][0] = *(const unsigned*)(As + base);
                a[mt][1] = *(const unsigned*)(As + base + 8 * PADK * 2);
                a[mt][2] = *(const unsigned*)(As + base + 16);
                a[mt][3] = *(const unsigned*)(As + base + 8 * PADK * 2 + 16);
            }
            unsigned bb[8][2];
#pragma unroll
            for (int nt = 0; nt < 8; nt++) {
                unsigned base = (unsigned)((wn + nt * 8 + g) * PADK + k0 + 2 * t) * 2;
                bb[nt][0] = *(const unsigned*)(Ws + base);
                bb[nt][1] = *(const unsigned*)(Ws + base + 16);
            }
#pragma unroll
            for (int mt = 0; mt < 2; mt++)
#pragma unroll
                for (int nt = 0; nt < 8; nt++)
                    mma_bf16(acc[mt][nt][0], acc[mt][nt][1], acc[mt][nt][2], acc[mt][nt][3],
                             a[mt][0], a[mt][1], a[mt][2], a[mt][3],
                             bb[nt][0], bb[nt][1]);
        }
    }
    __syncthreads();   // done reading A smem; Cs overlays it

    // stage results to smem (f32 [128][CS_STRIDE])
    {
        float* Cs = (float*)(sm + SM_CS);
#pragma unroll
        for (int mt = 0; mt < 2; mt++) {
            int r0 = wm + mt * 16 + g;
#pragma unroll
            for (int nt = 0; nt < 8; nt++) {
                int c = wn + nt * 8 + 2 * t;
                *(float2*)(Cs + r0 * CS_STRIDE + c) =
                    make_float2(acc[mt][nt][0], acc[mt][nt][1]);
                *(float2*)(Cs + (r0 + 8) * CS_STRIDE + c) =
                    make_float2(acc[mt][nt][2], acc[mt][nt][3]);
            }
        }
    }
    __syncthreads();

    // coalesced epilogue: bias + relu + float4 stores
    {
        const float* Cs = (const float*)(sm + SM_CS);
        int col4 = (tid & 31) * 4;
        int rbase = tid >> 5;
        float4 bv = *(const float4*)(sm + SM_BIAS + col4 * 4);
#pragma unroll
        for (int i = 0; i < 16; i++) {
            int r = rbase + i * 8;
            int gm = m0 + r;
            if (gm < M) {
                float4 v = *(const float4*)(Cs + r * CS_STRIDE + col4);
                float4 o;
                o.x = fmaxf(v.x + bv.x, 0.f);
                o.y = fmaxf(v.y + bv.y, 0.f);
                o.z = fmaxf(v.z + bv.z, 0.f);
                o.w = fmaxf(v.w + bv.w, 0.f);
                *(float4*)(out + (size_t)gm * D + col4) = o;
            }
        }
    }
}

// ---------------------------------------------------------------------------
// Launch
// ---------------------------------------------------------------------------
extern "C" void kernel_launch(void* const* d_in, const int* in_sizes, int n_in,
                              void* d_out, int out_size) {
    const float* h    = (const float*)d_in[0];
    const int*   esrc = (const int*)d_in[1];
    const int*   edst = (const int*)d_in[2];
    const float* W    = (const float*)d_in[3];
    const float* b    = (const float*)d_in[4];
    float* out = (float*)d_out;

    int M = in_sizes[0] / D;   // 100000
    int E = in_sizes[1];       // 1600000

    cudaFuncSetAttribute(k_gemm_mma, cudaFuncAttributeMaxDynamicSharedMemorySize,
                         SM_TOTAL);

    k_prepw<<<1, 128>>>(W);
    k_zero<<<2048, 256>>>((float4*)out, out_size / 4);
    k_scatter<<<(E + 255) / 256, 256>>>(h, esrc, edst, out, E);
    k_gemm_mma<<<(M + 127) / 128, 256, SM_TOTAL>>>(out, b, out, M);
}

// round 5
// speedup vs baseline: 1.2015x; 1.1564x over previous
#include <cuda_runtime.h>
#include <cuda_bf16.h>
#include <cstdint>

#define D 128
#define PADK 136            // padded bf16 row stride (conflict-free fragments)
#define W_IMG_U32 (128 * PADK / 2)   // 8704 u32 per image

// ---------------- scratch (static device mem) ------------------------------
__device__ unsigned g_Whi[W_IMG_U32];   // W bf16-hi, [n][PADK] layout
__device__ unsigned g_Wlo[W_IMG_U32];   // W bf16-lo

__device__ __forceinline__ unsigned pack_bf16x2(__nv_bfloat16 a, __nv_bfloat16 b) {
    return ((unsigned)*(unsigned short*)&a) | ((unsigned)*(unsigned short*)&b << 16);
}

// ---------------------------------------------------------------------------
// Kernel: W -> bf16 hi/lo padded images. 128 blocks x 64 threads.
// ---------------------------------------------------------------------------
__global__ void k_prepw(const float* __restrict__ W) {
    int n = blockIdx.x;            // W row
    int k = threadIdx.x * 2;       // bf16 pair
    float f0 = W[n * D + k], f1 = W[n * D + k + 1];
    __nv_bfloat16 h0 = __float2bfloat16(f0);
    __nv_bfloat16 h1 = __float2bfloat16(f1);
    __nv_bfloat16 l0 = __float2bfloat16(f0 - __bfloat162float(h0));
    __nv_bfloat16 l1 = __float2bfloat16(f1 - __bfloat162float(h1));
    unsigned idx = (unsigned)(n * PADK + k) / 2;
    g_Whi[idx] = pack_bf16x2(h0, h1);
    g_Wlo[idx] = pack_bf16x2(l0, l1);
}

// ---------------------------------------------------------------------------
// Kernel: zero accumulator (lives in d_out)
// ---------------------------------------------------------------------------
__global__ void k_zero(float4* __restrict__ out, int n4) {
    int i = blockIdx.x * blockDim.x + threadIdx.x;
    int stride = gridDim.x * blockDim.x;
    float4 z = make_float4(0.f, 0.f, 0.f, 0.f);
    for (; i < n4; i += stride) out[i] = z;
}

// ---------------------------------------------------------------------------
// Kernel: edge scatter-sum (proven R1). red.global.add.v4.f32.
// ---------------------------------------------------------------------------
__device__ __forceinline__ void red_add_v4(float* addr, float4 v) {
    asm volatile("red.global.add.v4.f32 [%0], {%1,%2,%3,%4};"
                 :: "l"(addr), "f"(v.x), "f"(v.y), "f"(v.z), "f"(v.w)
                 : "memory");
}

__global__ void k_scatter(const float* __restrict__ h,
                          const int* __restrict__ src,
                          const int* __restrict__ dst,
                          float* __restrict__ acc, int E) {
    int warp = (blockIdx.x * blockDim.x + threadIdx.x) >> 5;
    int lane = threadIdx.x & 31;
    int base = warp * 32;
    if (base >= E) return;

    int e = base + lane;
    int s = 0, d = 0;
    if (e < E) { s = src[e]; d = dst[e]; }
    int cnt = min(32, E - base);

    for (int i = 0; i < cnt; i++) {
        int si = __shfl_sync(0xffffffffu, s, i);
        int di = __shfl_sync(0xffffffffu, d, i);
        float4 v = *(const float4*)(h + (size_t)si * D + lane * 4);
        red_add_v4(acc + (size_t)di * D + lane * 4, v);
    }
}

// ---------------------------------------------------------------------------
// Tensor-core GEMM (mma.sync HMMA): out = relu(acc @ W^T + b), in place.
// CTA 128x128, 8 warps (4m x 2n), warp 32x64, 3-pass 2-term bf16 split.
// Register-pressure controlled: pass loop NOT unrolled, no smem C staging.
// ---------------------------------------------------------------------------
#define SM_WHI 0
#define SM_WLO (SM_WHI + 128 * PADK * 2)      // 34816
#define SM_AHI (SM_WLO + 128 * PADK * 2)      // 69632
#define SM_ALO (SM_AHI + 128 * PADK * 2)      // 104448
#define SM_BIAS (SM_ALO + 128 * PADK * 2)     // 139264
#define SM_TOTAL (SM_BIAS + 512)              // 139776

__device__ __forceinline__ void mma_bf16(float& c0, float& c1, float& c2, float& c3,
                                         unsigned a0, unsigned a1, unsigned a2, unsigned a3,
                                         unsigned b0, unsigned b1) {
    asm volatile(
        "mma.sync.aligned.m16n8k16.row.col.f32.bf16.bf16.f32 "
        "{%0,%1,%2,%3}, {%4,%5,%6,%7}, {%8,%9}, {%0,%1,%2,%3};"
        : "+f"(c0), "+f"(c1), "+f"(c2), "+f"(c3)
        : "r"(a0), "r"(a1), "r"(a2), "r"(a3), "r"(b0), "r"(b1));
}

__global__ void __launch_bounds__(256)
k_gemm_mma(const float* __restrict__ A,      // [M,128] (== out)
           const float* __restrict__ bias,   // [128]
           float* __restrict__ out, int M) {
    extern __shared__ char sm[];
    int tid = threadIdx.x;
    int wid = tid >> 5;
    int lane = tid & 31;
    int m0 = blockIdx.x * 128;

    // stage bias
    if (tid < 128) *(float*)(sm + SM_BIAS + tid * 4) = bias[tid];

    // copy W hi/lo images (coalesced uint4, L2-broadcast across CTAs)
    {
        const uint4* shi = (const uint4*)g_Whi;
        const uint4* slo = (const uint4*)g_Wlo;
        uint4* dhi = (uint4*)(sm + SM_WHI);
        uint4* dlo = (uint4*)(sm + SM_WLO);
        for (int i = tid; i < W_IMG_U32 / 4; i += 256) {
            dhi[i] = shi[i];
            dlo[i] = slo[i];
        }
    }

    // load + split A tile, fully coalesced: idx -> (row = idx>>5, col4 = (idx&31)*4)
    {
        char* ahi = sm + SM_AHI;
        char* alo = sm + SM_ALO;
#pragma unroll
        for (int j = 0; j < 16; j++) {
            int idx = j * 256 + tid;
            int row = idx >> 5;
            int c = (idx & 31) * 4;
            int gm = m0 + row;
            float4 v = make_float4(0.f, 0.f, 0.f, 0.f);
            if (gm < M) v = *(const float4*)(A + (size_t)gm * D + c);
            __nv_bfloat16 h0 = __float2bfloat16(v.x);
            __nv_bfloat16 h1 = __float2bfloat16(v.y);
            __nv_bfloat16 h2 = __float2bfloat16(v.z);
            __nv_bfloat16 h3 = __float2bfloat16(v.w);
            __nv_bfloat16 l0 = __float2bfloat16(v.x - __bfloat162float(h0));
            __nv_bfloat16 l1 = __float2bfloat16(v.y - __bfloat162float(h1));
            __nv_bfloat16 l2 = __float2bfloat16(v.z - __bfloat162float(h2));
            __nv_bfloat16 l3 = __float2bfloat16(v.w - __bfloat162float(h3));
            unsigned o = (unsigned)(row * PADK + c) * 2;
            *(uint2*)(ahi + o) = make_uint2(pack_bf16x2(h0, h1), pack_bf16x2(h2, h3));
            *(uint2*)(alo + o) = make_uint2(pack_bf16x2(l0, l1), pack_bf16x2(l2, l3));
        }
    }
    __syncthreads();

    int wm = (wid & 3) * 32;      // warp rows
    int wn = (wid >> 2) * 64;     // warp cols
    int g = lane >> 2;            // 0..7
    int t = lane & 3;             // 0..3

    float acc[2][8][4];
#pragma unroll
    for (int mt = 0; mt < 2; mt++)
#pragma unroll
        for (int nt = 0; nt < 8; nt++)
#pragma unroll
            for (int i = 0; i < 4; i++) acc[mt][nt][i] = 0.f;

#pragma unroll 1
    for (int p = 0; p < 3; p++) {
        const char* As = sm + ((p == 2) ? SM_ALO : SM_AHI);
        const char* Ws = sm + ((p == 1) ? SM_WLO : SM_WHI);
#pragma unroll 1
        for (int ks = 0; ks < 8; ks++) {
            int k0 = ks * 16;
            unsigned a[2][4];
#pragma unroll
            for (int mt = 0; mt < 2; mt++) {
                unsigned base = (unsigned)((wm + mt * 16 + g) * PADK + k0 + 2 * t) * 2;
                a[mt][0] = *(const unsigned*)(As + base);
                a[mt][1] = *(const unsigned*)(As + base + 8 * PADK * 2);
                a[mt][2] = *(const unsigned*)(As + base + 16);
                a[mt][3] = *(const unsigned*)(As + base + 8 * PADK * 2 + 16);
            }
            unsigned bb[8][2];
#pragma unroll
            for (int nt = 0; nt < 8; nt++) {
                unsigned base = (unsigned)((wn + nt * 8 + g) * PADK + k0 + 2 * t) * 2;
                bb[nt][0] = *(const unsigned*)(Ws + base);
                bb[nt][1] = *(const unsigned*)(Ws + base + 16);
            }
#pragma unroll
            for (int mt = 0; mt < 2; mt++)
#pragma unroll
                for (int nt = 0; nt < 8; nt++)
                    mma_bf16(acc[mt][nt][0], acc[mt][nt][1], acc[mt][nt][2], acc[mt][nt][3],
                             a[mt][0], a[mt][1], a[mt][2], a[mt][3],
                             bb[nt][0], bb[nt][1]);
        }
    }

    // direct epilogue: bias + relu + float2 stores (32B-sector aligned groups)
    {
        const float* bs = (const float*)(sm + SM_BIAS);
#pragma unroll
        for (int mt = 0; mt < 2; mt++) {
            int r0 = wm + mt * 16 + g;
            int gm0 = m0 + r0;
            int gm1 = gm0 + 8;
#pragma unroll
            for (int nt = 0; nt < 8; nt++) {
                int c = wn + nt * 8 + 2 * t;
                float2 bv = *(const float2*)(bs + c);
                if (gm0 < M) {
                    float2 o;
                    o.x = fmaxf(acc[mt][nt][0] + bv.x, 0.f);
                    o.y = fmaxf(acc[mt][nt][1] + bv.y, 0.f);
                    *(float2*)(out + (size_t)gm0 * D + c) = o;
                }
                if (gm1 < M) {
                    float2 o;
                    o.x = fmaxf(acc[mt][nt][2] + bv.x, 0.f);
                    o.y = fmaxf(acc[mt][nt][3] + bv.y, 0.f);
                    *(float2*)(out + (size_t)gm1 * D + c) = o;
                }
            }
        }
    }
}

// ---------------------------------------------------------------------------
// Launch
// ---------------------------------------------------------------------------
extern "C" void kernel_launch(void* const* d_in, const int* in_sizes, int n_in,
                              void* d_out, int out_size) {
    const float* h    = (const float*)d_in[0];
    const int*   esrc = (const int*)d_in[1];
    const int*   edst = (const int*)d_in[2];
    const float* W    = (const float*)d_in[3];
    const float* b    = (const float*)d_in[4];
    float* out = (float*)d_out;

    int M = in_sizes[0] / D;   // 100000
    int E = in_sizes[1];       // 1600000

    cudaFuncSetAttribute(k_gemm_mma, cudaFuncAttributeMaxDynamicSharedMemorySize,
                         SM_TOTAL);

    k_prepw<<<128, 64>>>(W);
    k_zero<<<2048, 256>>>((float4*)out, out_size / 4);
    k_scatter<<<(E + 255) / 256, 256>>>(h, esrc, edst, out, E);
    k_gemm_mma<<<(M + 127) / 128, 256, SM_TOTAL>>>(out, b, out, M);
}

// round 6
// speedup vs baseline: 1.3918x; 1.1584x over previous
#include <cuda_runtime.h>
#include <cuda_bf16.h>
#include <cstdint>

#define D 128
#define MAXN 100000
#define MAXE 1600000
#define PADK 136            // padded bf16 row stride (conflict-free fragments)
#define W_IMG_U32 (128 * PADK / 2)   // 8704 u32 per image

// ---------------- scratch (static device mem) ------------------------------
__device__ unsigned g_Whi[W_IMG_U32];   // W bf16-hi, [n][PADK] layout
__device__ unsigned g_Wlo[W_IMG_U32];   // W bf16-lo
__device__ int g_cnt[MAXN];             // histogram -> fill cursors
__device__ int g_off[MAXN + 1];         // CSR row offsets
__device__ int g_csr[MAXE];             // edge srcs grouped by dst
__device__ int g_blk[256];              // scan partials

__device__ __forceinline__ unsigned pack_bf16x2(__nv_bfloat16 a, __nv_bfloat16 b) {
    return ((unsigned)*(unsigned short*)&a) | ((unsigned)*(unsigned short*)&b << 16);
}

// ---------------------------------------------------------------------------
// W -> bf16 hi/lo padded images. 128 blocks x 64 threads.
// ---------------------------------------------------------------------------
__global__ void k_prepw(const float* __restrict__ W) {
    int n = blockIdx.x;
    int k = threadIdx.x * 2;
    float f0 = W[n * D + k], f1 = W[n * D + k + 1];
    __nv_bfloat16 h0 = __float2bfloat16(f0);
    __nv_bfloat16 h1 = __float2bfloat16(f1);
    __nv_bfloat16 l0 = __float2bfloat16(f0 - __bfloat162float(h0));
    __nv_bfloat16 l1 = __float2bfloat16(f1 - __bfloat162float(h1));
    unsigned idx = (unsigned)(n * PADK + k) / 2;
    g_Whi[idx] = pack_bf16x2(h0, h1);
    g_Wlo[idx] = pack_bf16x2(l0, l1);
}

// ---------------------------------------------------------------------------
// CSR build: zero -> histogram -> 3-phase scan -> fill (R2-verified)
// ---------------------------------------------------------------------------
__global__ void k_zero_cnt(int n) {
    int i = blockIdx.x * blockDim.x + threadIdx.x;
    if (i < n) g_cnt[i] = 0;
}

__global__ void k_hist(const int* __restrict__ dst, int E) {
    int i = blockIdx.x * blockDim.x + threadIdx.x;
    int stride = gridDim.x * blockDim.x;
    for (; i < E; i += stride) atomicAdd(&g_cnt[dst[i]], 1);
}

__global__ void k_scan1(int n) {
    __shared__ int wsum[8];
    int b = blockIdx.x, t = threadIdx.x;
    int base = b * 1024 + t * 4;
    int v0 = (base + 0 < n) ? g_cnt[base + 0] : 0;
    int v1 = (base + 1 < n) ? g_cnt[base + 1] : 0;
    int v2 = (base + 2 < n) ? g_cnt[base + 2] : 0;
    int v3 = (base + 3 < n) ? g_cnt[base + 3] : 0;
    int s = v0 + v1 + v2 + v3;

    int lane = t & 31, w = t >> 5;
    int inc = s;
#pragma unroll
    for (int o = 1; o < 32; o <<= 1) {
        int x = __shfl_up_sync(0xffffffffu, inc, o);
        if (lane >= o) inc += x;
    }
    if (lane == 31) wsum[w] = inc;
    __syncthreads();
    if (t == 0) {
        int run = 0;
#pragma unroll
        for (int i = 0; i < 8; i++) { int tmp = wsum[i]; wsum[i] = run; run += tmp; }
        g_blk[b] = run;
    }
    __syncthreads();
    int excl = wsum[w] + inc - s;
    if (base + 0 < n) g_off[base + 0] = excl;
    if (base + 1 < n) g_off[base + 1] = excl + v0;
    if (base + 2 < n) g_off[base + 2] = excl + v0 + v1;
    if (base + 3 < n) g_off[base + 3] = excl + v0 + v1 + v2;
}

__global__ void k_scan2(int nb) {
    __shared__ int s[256];
    int t = threadIdx.x;
    s[t] = (t < nb) ? g_blk[t] : 0;
    __syncthreads();
    if (t == 0) {
        int run = 0;
        for (int i = 0; i < nb; i++) { int tmp = s[i]; s[i] = run; run += tmp; }
    }
    __syncthreads();
    if (t < nb) g_blk[t] = s[t];
}

__global__ void k_scan3(int n, int E) {
    int i = blockIdx.x * blockDim.x + threadIdx.x;
    if (i < n) {
        int v = g_off[i] + g_blk[i >> 10];
        g_off[i] = v;
        g_cnt[i] = v;
    }
    if (i == 0) g_off[n] = E;
}

__global__ void k_fill(const int* __restrict__ src, const int* __restrict__ dst, int E) {
    int i = blockIdx.x * blockDim.x + threadIdx.x;
    int stride = gridDim.x * blockDim.x;
    for (; i < E; i += stride) {
        int pos = atomicAdd(&g_cnt[dst[i]], 1);
        g_csr[pos] = src[i];
    }
}

// ---------------------------------------------------------------------------
// Gather: acc[n] = sum_{e in CSR[n]} h[src[e]]. Warp per node, lane owns 16B.
// unroll-4 (MLP=4). Writes every row -> no zero kernel needed.
// ---------------------------------------------------------------------------
__global__ void k_gather(const float* __restrict__ h, float* __restrict__ acc, int N) {
    int node = blockIdx.x * 8 + (threadIdx.x >> 5);
    if (node >= N) return;
    int lane = threadIdx.x & 31;

    int beg = g_off[node];
    int end = g_off[node + 1];

    float4 a0 = make_float4(0.f, 0.f, 0.f, 0.f);
    float4 a1 = make_float4(0.f, 0.f, 0.f, 0.f);
    float4 a2 = make_float4(0.f, 0.f, 0.f, 0.f);
    float4 a3 = make_float4(0.f, 0.f, 0.f, 0.f);

    int e = beg;
    for (; e + 3 < end; e += 4) {
        int s0 = __ldg(&g_csr[e]);
        int s1 = __ldg(&g_csr[e + 1]);
        int s2 = __ldg(&g_csr[e + 2]);
        int s3 = __ldg(&g_csr[e + 3]);
        float4 v0 = __ldg((const float4*)(h + (size_t)s0 * D + lane * 4));
        float4 v1 = __ldg((const float4*)(h + (size_t)s1 * D + lane * 4));
        float4 v2 = __ldg((const float4*)(h + (size_t)s2 * D + lane * 4));
        float4 v3 = __ldg((const float4*)(h + (size_t)s3 * D + lane * 4));
        a0.x += v0.x; a0.y += v0.y; a0.z += v0.z; a0.w += v0.w;
        a1.x += v1.x; a1.y += v1.y; a1.z += v1.z; a1.w += v1.w;
        a2.x += v2.x; a2.y += v2.y; a2.z += v2.z; a2.w += v2.w;
        a3.x += v3.x; a3.y += v3.y; a3.z += v3.z; a3.w += v3.w;
    }
    for (; e < end; e++) {
        int s0 = __ldg(&g_csr[e]);
        float4 v0 = __ldg((const float4*)(h + (size_t)s0 * D + lane * 4));
        a0.x += v0.x; a0.y += v0.y; a0.z += v0.z; a0.w += v0.w;
    }
    float4 o;
    o.x = (a0.x + a1.x) + (a2.x + a3.x);
    o.y = (a0.y + a1.y) + (a2.y + a3.y);
    o.z = (a0.z + a1.z) + (a2.z + a3.z);
    o.w = (a0.w + a1.w) + (a2.w + a3.w);
    *(float4*)(acc + (size_t)node * D + lane * 4) = o;
}

// ---------------------------------------------------------------------------
// Tensor-core GEMM (mma.sync HMMA) — unchanged from R5 (proven 63.1 us).
// ---------------------------------------------------------------------------
#define SM_WHI 0
#define SM_WLO (SM_WHI + 128 * PADK * 2)
#define SM_AHI (SM_WLO + 128 * PADK * 2)
#define SM_ALO (SM_AHI + 128 * PADK * 2)
#define SM_BIAS (SM_ALO + 128 * PADK * 2)
#define SM_TOTAL (SM_BIAS + 512)

__device__ __forceinline__ void mma_bf16(float& c0, float& c1, float& c2, float& c3,
                                         unsigned a0, unsigned a1, unsigned a2, unsigned a3,
                                         unsigned b0, unsigned b1) {
    asm volatile(
        "mma.sync.aligned.m16n8k16.row.col.f32.bf16.bf16.f32 "
        "{%0,%1,%2,%3}, {%4,%5,%6,%7}, {%8,%9}, {%0,%1,%2,%3};"
        : "+f"(c0), "+f"(c1), "+f"(c2), "+f"(c3)
        : "r"(a0), "r"(a1), "r"(a2), "r"(a3), "r"(b0), "r"(b1));
}

__global__ void __launch_bounds__(256)
k_gemm_mma(const float* __restrict__ A,
           const float* __restrict__ bias,
           float* __restrict__ out, int M) {
    extern __shared__ char sm[];
    int tid = threadIdx.x;
    int wid = tid >> 5;
    int lane = tid & 31;
    int m0 = blockIdx.x * 128;

    if (tid < 128) *(float*)(sm + SM_BIAS + tid * 4) = bias[tid];

    {
        const uint4* shi = (const uint4*)g_Whi;
        const uint4* slo = (const uint4*)g_Wlo;
        uint4* dhi = (uint4*)(sm + SM_WHI);
        uint4* dlo = (uint4*)(sm + SM_WLO);
        for (int i = tid; i < W_IMG_U32 / 4; i += 256) {
            dhi[i] = shi[i];
            dlo[i] = slo[i];
        }
    }

    {
        char* ahi = sm + SM_AHI;
        char* alo = sm + SM_ALO;
#pragma unroll
        for (int j = 0; j < 16; j++) {
            int idx = j * 256 + tid;
            int row = idx >> 5;
            int c = (idx & 31) * 4;
            int gm = m0 + row;
            float4 v = make_float4(0.f, 0.f, 0.f, 0.f);
            if (gm < M) v = *(const float4*)(A + (size_t)gm * D + c);
            __nv_bfloat16 h0 = __float2bfloat16(v.x);
            __nv_bfloat16 h1 = __float2bfloat16(v.y);
            __nv_bfloat16 h2 = __float2bfloat16(v.z);
            __nv_bfloat16 h3 = __float2bfloat16(v.w);
            __nv_bfloat16 l0 = __float2bfloat16(v.x - __bfloat162float(h0));
            __nv_bfloat16 l1 = __float2bfloat16(v.y - __bfloat162float(h1));
            __nv_bfloat16 l2 = __float2bfloat16(v.z - __bfloat162float(h2));
            __nv_bfloat16 l3 = __float2bfloat16(v.w - __bfloat162float(h3));
            unsigned o = (unsigned)(row * PADK + c) * 2;
            *(uint2*)(ahi + o) = make_uint2(pack_bf16x2(h0, h1), pack_bf16x2(h2, h3));
            *(uint2*)(alo + o) = make_uint2(pack_bf16x2(l0, l1), pack_bf16x2(l2, l3));
        }
    }
    __syncthreads();

    int wm = (wid & 3) * 32;
    int wn = (wid >> 2) * 64;
    int g = lane >> 2;
    int t = lane & 3;

    float acc[2][8][4];
#pragma unroll
    for (int mt = 0; mt < 2; mt++)
#pragma unroll
        for (int nt = 0; nt < 8; nt++)
#pragma unroll
            for (int i = 0; i < 4; i++) acc[mt][nt][i] = 0.f;

#pragma unroll 1
    for (int p = 0; p < 3; p++) {
        const char* As = sm + ((p == 2) ? SM_ALO : SM_AHI);
        const char* Ws = sm + ((p == 1) ? SM_WLO : SM_WHI);
#pragma unroll 1
        for (int ks = 0; ks < 8; ks++) {
            int k0 = ks * 16;
            unsigned a[2][4];
#pragma unroll
            for (int mt = 0; mt < 2; mt++) {
                unsigned base = (unsigned)((wm + mt * 16 + g) * PADK + k0 + 2 * t) * 2;
                a[mt][0] = *(const unsigned*)(As + base);
                a[mt][1] = *(const unsigned*)(As + base + 8 * PADK * 2);
                a[mt][2] = *(const unsigned*)(As + base + 16);
                a[mt][3] = *(const unsigned*)(As + base + 8 * PADK * 2 + 16);
            }
            unsigned bb[8][2];
#pragma unroll
            for (int nt = 0; nt < 8; nt++) {
                unsigned base = (unsigned)((wn + nt * 8 + g) * PADK + k0 + 2 * t) * 2;
                bb[nt][0] = *(const unsigned*)(Ws + base);
                bb[nt][1] = *(const unsigned*)(Ws + base + 16);
            }
#pragma unroll
            for (int mt = 0; mt < 2; mt++)
#pragma unroll
                for (int nt = 0; nt < 8; nt++)
                    mma_bf16(acc[mt][nt][0], acc[mt][nt][1], acc[mt][nt][2], acc[mt][nt][3],
                             a[mt][0], a[mt][1], a[mt][2], a[mt][3],
                             bb[nt][0], bb[nt][1]);
        }
    }

    {
        const float* bs = (const float*)(sm + SM_BIAS);
#pragma unroll
        for (int mt = 0; mt < 2; mt++) {
            int r0 = wm + mt * 16 + g;
            int gm0 = m0 + r0;
            int gm1 = gm0 + 8;
#pragma unroll
            for (int nt = 0; nt < 8; nt++) {
                int c = wn + nt * 8 + 2 * t;
                float2 bv = *(const float2*)(bs + c);
                if (gm0 < M) {
                    float2 o;
                    o.x = fmaxf(acc[mt][nt][0] + bv.x, 0.f);
                    o.y = fmaxf(acc[mt][nt][1] + bv.y, 0.f);
                    *(float2*)(out + (size_t)gm0 * D + c) = o;
                }
                if (gm1 < M) {
                    float2 o;
                    o.x = fmaxf(acc[mt][nt][2] + bv.x, 0.f);
                    o.y = fmaxf(acc[mt][nt][3] + bv.y, 0.f);
                    *(float2*)(out + (size_t)gm1 * D + c) = o;
                }
            }
        }
    }
}

// ---------------------------------------------------------------------------
// Launch
// ---------------------------------------------------------------------------
extern "C" void kernel_launch(void* const* d_in, const int* in_sizes, int n_in,
                              void* d_out, int out_size) {
    const float* h    = (const float*)d_in[0];
    const int*   esrc = (const int*)d_in[1];
    const int*   edst = (const int*)d_in[2];
    const float* W    = (const float*)d_in[3];
    const float* b    = (const float*)d_in[4];
    float* out = (float*)d_out;

    int M = in_sizes[0] / D;   // 100000
    int E = in_sizes[1];       // 1600000

    cudaFuncSetAttribute(k_gemm_mma, cudaFuncAttributeMaxDynamicSharedMemorySize,
                         SM_TOTAL);

    int nb = (M + 1023) / 1024;

    k_prepw<<<128, 64>>>(W);
    k_zero_cnt<<<(M + 255) / 256, 256>>>(M);
    k_hist<<<1024, 256>>>(edst, E);
    k_scan1<<<nb, 256>>>(M);
    k_scan2<<<1, 256>>>(nb);
    k_scan3<<<(M + 255) / 256, 256>>>(M, E);
    k_fill<<<1024, 256>>>(esrc, edst, E);
    k_gather<<<(M + 7) / 8, 256>>>(h, out, M);
    k_gemm_mma<<<(M + 127) / 128, 256, SM_TOTAL>>>(out, b, out, M);
}